// round 2
// baseline (speedup 1.0000x reference)
#include <cuda_runtime.h>
#include <math.h>

// Problem constants
#define BATCH 4096
#define HID   1024
#define INDIM 1024
// Virtual GEMM N layout in scratch: [0,3072)=i,f,o  [3072,4096)=cand  [4096,5120)=s
#define NV    5120

#define BM 128
#define BN 128
#define BK 16
#define NTHREADS 256

// Scratch: 4096 x 5120 fp32 (~84 MB) — static device array (allowed; no runtime alloc)
__device__ float g_C[(size_t)BATCH * NV];

__global__ __launch_bounds__(NTHREADS, 2)
void srul_gemm_kernel(const float* __restrict__ x,
                      const float* __restrict__ h,
                      const float* __restrict__ Wi,
                      const float* __restrict__ Wf,
                      const float* __restrict__ Wo,
                      const float* __restrict__ Wxs,
                      const float* __restrict__ Wxg,
                      const float* __restrict__ Whg)
{
    __shared__ float As[BK][BM + 4];
    __shared__ float Ws[BK][BN + 4];

    const int tid = threadIdx.x;
    const int bm0 = blockIdx.x * BM;          // batch-row base
    const int n0  = blockIdx.y * BN;          // virtual-N base

    // ---- select weight region for this N tile (BN=128 never straddles a 1024 boundary) ----
    const float* Wlo;       // rows for k in [0,1024)   (A = x)
    const float* Whi;       // rows for k in [1024,2048) (A = h), nullptr if K==1024
    int wstride;
    if (n0 < 3072) {
        const float* Wsel = (n0 < 1024) ? Wi : (n0 < 2048) ? Wf : Wo;
        int rr = n0 & 1023;
        Wlo = Wsel + (size_t)rr * 2048;
        Whi = Wsel + (size_t)rr * 2048 + 1024;
        wstride = 2048;
    } else if (n0 < 4096) {
        int rr = n0 - 3072;
        Wlo = Wxg + (size_t)rr * 1024;
        Whi = Whg + (size_t)rr * 1024;
        wstride = 1024;
    } else {
        int rr = n0 - 4096;
        Wlo = Wxs + (size_t)rr * 1024;
        Whi = nullptr;
        wstride = 1024;
    }

    float acc[8][8];
    #pragma unroll
    for (int i = 0; i < 8; ++i)
        #pragma unroll
        for (int j = 0; j < 8; ++j) acc[i][j] = 0.f;

    const int lr = tid >> 2;            // 0..63 : row within tile
    const int lc = (tid & 3) * 4;       // 0,4,8,12 : col (float) within k-tile
    const int tm = (tid >> 4) * 8;      // thread micro-tile m base
    const int tn = (tid & 15) * 8;      // thread micro-tile n base

    #pragma unroll 1
    for (int phase = 0; phase < 2; ++phase) {
        const float* A = phase ? h : x;               // both [4096,1024], stride 1024
        const float* W = phase ? Whi : Wlo;
        if (W == nullptr) break;

        #pragma unroll 1
        for (int kt = 0; kt < 1024; kt += BK) {
            // ---- global -> shared (transposed store) ----
            float4 a0 = *(const float4*)(A + (size_t)(bm0 + lr)      * 1024 + kt + lc);
            float4 a1 = *(const float4*)(A + (size_t)(bm0 + lr + 64) * 1024 + kt + lc);
            float4 w0 = *(const float4*)(W + (size_t)(lr)      * wstride + kt + lc);
            float4 w1 = *(const float4*)(W + (size_t)(lr + 64) * wstride + kt + lc);

            __syncthreads();   // protect previous iteration's reads
            As[lc + 0][lr] = a0.x;  As[lc + 1][lr] = a0.y;  As[lc + 2][lr] = a0.z;  As[lc + 3][lr] = a0.w;
            As[lc + 0][lr + 64] = a1.x; As[lc + 1][lr + 64] = a1.y; As[lc + 2][lr + 64] = a1.z; As[lc + 3][lr + 64] = a1.w;
            Ws[lc + 0][lr] = w0.x;  Ws[lc + 1][lr] = w0.y;  Ws[lc + 2][lr] = w0.z;  Ws[lc + 3][lr] = w0.w;
            Ws[lc + 0][lr + 64] = w1.x; Ws[lc + 1][lr + 64] = w1.y; Ws[lc + 2][lr + 64] = w1.z; Ws[lc + 3][lr + 64] = w1.w;
            __syncthreads();

            // ---- rank-1 updates ----
            #pragma unroll
            for (int kk = 0; kk < BK; ++kk) {
                float a[8], b[8];
                *(float4*)(a)     = *(const float4*)&As[kk][tm];
                *(float4*)(a + 4) = *(const float4*)&As[kk][tm + 4];
                *(float4*)(b)     = *(const float4*)&Ws[kk][tn];
                *(float4*)(b + 4) = *(const float4*)&Ws[kk][tn + 4];
                #pragma unroll
                for (int i = 0; i < 8; ++i)
                    #pragma unroll
                    for (int j = 0; j < 8; ++j)
                        acc[i][j] = fmaf(a[i], b[j], acc[i][j]);
            }
        }
    }

    // ---- write tile to scratch ----
    #pragma unroll
    for (int i = 0; i < 8; ++i) {
        float* dst = g_C + (size_t)(bm0 + tm + i) * NV + (n0 + tn);
        *(float4*)(dst)     = *(float4*)&acc[i][0];
        *(float4*)(dst + 4) = *(float4*)&acc[i][4];
    }
}

__device__ __forceinline__ float sigmoidf_(float v) {
    return 1.0f / (1.0f + expf(-v));
}

__global__ __launch_bounds__(256)
void srul_epilogue_kernel(const float* __restrict__ c_prev,
                          const float* __restrict__ bi,
                          const float* __restrict__ bf,
                          const float* __restrict__ bo,
                          const float* __restrict__ bxs,
                          const float* __restrict__ bxg,
                          const float* __restrict__ bhg,
                          float* __restrict__ out)
{
    int idx = blockIdx.x * blockDim.x + threadIdx.x;   // each thread: 4 elems
    int v = idx * 4;
    if (v >= BATCH * HID) return;
    int b = v >> 10;
    int j = v & 1023;

    const float* row = g_C + (size_t)b * NV;
    float4 ri = *(const float4*)(row + j);
    float4 rf = *(const float4*)(row + 1024 + j);
    float4 ro = *(const float4*)(row + 2048 + j);
    float4 rc = *(const float4*)(row + 3072 + j);
    float4 rs = *(const float4*)(row + 4096 + j);
    float4 vbi  = *(const float4*)(bi + j);
    float4 vbf  = *(const float4*)(bf + j);
    float4 vbo  = *(const float4*)(bo + j);
    float4 vbxs = *(const float4*)(bxs + j);
    float4 vbxg = *(const float4*)(bxg + j);
    float4 vbhg = *(const float4*)(bhg + j);
    float4 vcp  = *(const float4*)(c_prev + (size_t)b * 1024 + j);

    float4 outh, outc;
    const float* pri = &ri.x; const float* prf = &rf.x; const float* pro = &ro.x;
    const float* prc = &rc.x; const float* prs = &rs.x;
    const float* pbi = &vbi.x; const float* pbf = &vbf.x; const float* pbo = &vbo.x;
    const float* pbxs = &vbxs.x; const float* pbxg = &vbxg.x; const float* pbhg = &vbhg.x;
    const float* pcp = &vcp.x;
    float* ph = &outh.x; float* pc = &outc.x;

    #pragma unroll
    for (int t = 0; t < 4; ++t) {
        float ig = sigmoidf_(pri[t] + pbi[t]);
        float fg = sigmoidf_(prf[t] + pbf[t]);
        float og = sigmoidf_(pro[t] + pbo[t]);
        float s  = prs[t] + pbxs[t];
        float cand = prc[t] + pbxg[t] + pbhg[t];
        float g  = tanhf(s * cand);
        float c  = fg * pcp[t] + ig * g;
        float hh = og * tanhf(c);
        ph[t] = hh;
        pc[t] = c;
    }

    // output layout: [h_t (4096x1024); c_t (4096x1024)]
    *(float4*)(out + (size_t)b * 1024 + j) = outh;
    *(float4*)(out + (size_t)BATCH * HID + (size_t)b * 1024 + j) = outc;
}

extern "C" void kernel_launch(void* const* d_in, const int* in_sizes, int n_in,
                              void* d_out, int out_size)
{
    const float* x      = (const float*)d_in[0];
    const float* h_prev = (const float*)d_in[1];
    const float* c_prev = (const float*)d_in[2];
    const float* Wi     = (const float*)d_in[3];
    const float* bi     = (const float*)d_in[4];
    const float* Wf     = (const float*)d_in[5];
    const float* bf     = (const float*)d_in[6];
    const float* Wo     = (const float*)d_in[7];
    const float* bo     = (const float*)d_in[8];
    const float* Wxs    = (const float*)d_in[9];
    const float* bxs    = (const float*)d_in[10];
    const float* Wxg    = (const float*)d_in[11];
    const float* bxg    = (const float*)d_in[12];
    const float* Whg    = (const float*)d_in[13];
    const float* bhg    = (const float*)d_in[14];
    float* out = (float*)d_out;

    dim3 grid(BATCH / BM, NV / BN);   // 32 x 40
    srul_gemm_kernel<<<grid, NTHREADS>>>(x, h_prev, Wi, Wf, Wo, Wxs, Wxg, Whg);

    int total_vec = (BATCH * HID) / 4;            // 1M threads
    srul_epilogue_kernel<<<(total_vec + 255) / 256, 256>>>(c_prev, bi, bf, bo, bxs, bxg, bhg, out);
}

// round 5
// speedup vs baseline: 1.0226x; 1.0226x over previous
#include <cuda_runtime.h>
#include <cuda_bf16.h>
#include <cstdint>
#include <math.h>

#define BATCH 4096
#define HID   1024
#define NV    5120          // virtual N: [0,3072)=i,f,o  [3072,4096)=cand  [4096,5120)=s
#define KA    4096          // A cols: [0,2048)=hi(concat(x,h))  [2048,4096)=lo
#define KB    4096
#define BM    128
#define BN    128
#define BK    32
#define NSTG  4
#define KT    192           // 3 passes * (2048/32)

#define ROWH  40            // smem row stride in bf16 elems (64B data + 16B pad)
#define TILE_BYTES (128 * ROWH * 2)          // 10240 per operand tile
#define STAGE_BYTES (2 * TILE_BYTES)         // A + B
#define SMEM_DYN (NSTG * STAGE_BYTES)        // 81920

// device scratch (static — no runtime allocation)
__device__ __nv_bfloat16 g_A[(size_t)BATCH * KA];    // 32 MB
__device__ __nv_bfloat16 g_B[(size_t)NV * KB];       // 40 MB
__device__ float          g_C[(size_t)BATCH * NV];   // 80 MB

// ---------------- helpers ----------------
__device__ __forceinline__ uint32_t smem_u32(const void* p) {
    uint32_t a;
    asm("{ .reg .u64 t; cvta.to.shared.u64 t, %1; cvt.u32.u64 %0, t; }" : "=r"(a) : "l"(p));
    return a;
}
__device__ __forceinline__ void cp_async16(uint32_t dst, const void* src) {
    asm volatile("cp.async.cg.shared.global [%0], [%1], 16;" :: "r"(dst), "l"(src));
}
__device__ __forceinline__ void cp_commit() { asm volatile("cp.async.commit_group;" ::: "memory"); }
__device__ __forceinline__ void cp_wait2()  { asm volatile("cp.async.wait_group 2;"  ::: "memory"); }

__device__ __forceinline__ void mma16816(float* c, const uint32_t* a, const uint32_t* b) {
    asm volatile("mma.sync.aligned.m16n8k16.row.col.f32.bf16.bf16.f32 "
                 "{%0,%1,%2,%3}, {%4,%5,%6,%7}, {%8,%9}, {%0,%1,%2,%3};"
                 : "+f"(c[0]), "+f"(c[1]), "+f"(c[2]), "+f"(c[3])
                 : "r"(a[0]), "r"(a[1]), "r"(a[2]), "r"(a[3]), "r"(b[0]), "r"(b[1]));
}

// ---------------- conversion kernels ----------------
__global__ __launch_bounds__(256) void convA_kernel(const float* __restrict__ x,
                                                    const float* __restrict__ h) {
    int idx = blockIdx.x * 256 + threadIdx.x;            // over 4096*2048
    if (idx >= BATCH * 2048) return;
    int m = idx >> 11, k = idx & 2047;
    float v = (k < 1024) ? x[(size_t)m * 1024 + k] : h[(size_t)m * 1024 + (k - 1024)];
    __nv_bfloat16 hi = __float2bfloat16(v);
    __nv_bfloat16 lo = __float2bfloat16(v - __bfloat162float(hi));
    g_A[(size_t)m * KA + k] = hi;
    g_A[(size_t)m * KA + 2048 + k] = lo;
}

__global__ __launch_bounds__(256) void convB_kernel(const float* __restrict__ Wi,
                                                    const float* __restrict__ Wf,
                                                    const float* __restrict__ Wo,
                                                    const float* __restrict__ Wxs,
                                                    const float* __restrict__ Wxg,
                                                    const float* __restrict__ Whg) {
    int idx = blockIdx.x * 256 + threadIdx.x;            // over 5120*2048
    if (idx >= NV * 2048) return;
    int n = idx >> 11, k = idx & 2047;
    float v;
    if (n < 3072) {
        const float* W = (n < 1024) ? Wi : (n < 2048) ? Wf : Wo;
        v = W[(size_t)(n & 1023) * 2048 + k];
    } else if (n < 4096) {
        int rr = n - 3072;
        v = (k < 1024) ? Wxg[(size_t)rr * 1024 + k] : Whg[(size_t)rr * 1024 + (k - 1024)];
    } else {
        int rr = n - 4096;
        v = (k < 1024) ? Wxs[(size_t)rr * 1024 + k] : 0.0f;
    }
    __nv_bfloat16 hi = __float2bfloat16(v);
    __nv_bfloat16 lo = __float2bfloat16(v - __bfloat162float(hi));
    g_B[(size_t)n * KB + k] = hi;
    g_B[(size_t)n * KB + 2048 + k] = lo;
}

// ---------------- HMMA GEMM ----------------
__global__ void __launch_bounds__(256) gemm_kernel() {
    extern __shared__ char smem_dyn[];

    const int tid  = threadIdx.x;
    const int wid  = tid >> 5;
    const int lane = tid & 31;
    const int g    = lane >> 2;        // group 0..7
    const int tig  = lane & 3;         // 0..3
    const int wm   = wid >> 1;         // warp m index 0..3 (32 rows each)
    const int wn   = wid & 1;          // warp n index 0..1 (64 cols each)
    const int bm0  = blockIdx.x * BM;
    const int n0   = blockIdx.y * BN;

    const uint32_t smem0 = smem_u32(smem_dyn);
    const int lrow = tid >> 1;                 // 0..127 : row loaded by this thread
    const int lch0 = (tid & 1) * 2;            // chunks {0,1} or {2,3}

    // stage loader: tile `it` into slot `s` (each thread: 2 chunks A + 2 chunks B)
    auto load_stage = [&](int s, int it) {
        int pass = it >> 6;                    // 0: hi*hi  1: hi*lo  2: lo*hi
        int kk   = (it & 63) * BK;
        int acol = ((pass == 2) ? 2048 : 0) + kk;
        int bcol = ((pass == 1) ? 2048 : 0) + kk;
        uint32_t baseA = smem0 + s * STAGE_BYTES;
        uint32_t baseB = baseA + TILE_BYTES;
        const __nv_bfloat16* srcA = g_A + (size_t)(bm0 + lrow) * KA + acol;
        const __nv_bfloat16* srcB = g_B + (size_t)(n0  + lrow) * KB + bcol;
        uint32_t rowoff = lrow * (ROWH * 2);
        #pragma unroll
        for (int c = 0; c < 2; ++c) {
            int ch = lch0 + c;
            cp_async16(baseA + rowoff + ch * 16, srcA + ch * 8);
            cp_async16(baseB + rowoff + ch * 16, srcB + ch * 8);
        }
    };

    float acc[2][8][4];
    #pragma unroll
    for (int i = 0; i < 2; ++i)
        #pragma unroll
        for (int j = 0; j < 8; ++j)
            #pragma unroll
            for (int t = 0; t < 4; ++t) acc[i][j][t] = 0.f;

    // prologue: stages 0..2
    #pragma unroll
    for (int p = 0; p < NSTG - 1; ++p) { load_stage(p, p); cp_commit(); }

    for (int it = 0; it < KT; ++it) {
        int s = it & 3;
        cp_wait2();             // tile `it` complete (this thread)
        __syncthreads();        // all threads' chunks visible; prev compute done

        // prefetch tile it+3 into stage (it+3)&3  (== (it-1)&3, safe after barrier)
        if (it + NSTG - 1 < KT) load_stage((it + NSTG - 1) & 3, it + NSTG - 1);
        cp_commit();            // unconditional: keeps group accounting exact at tail

        const __nv_bfloat16* As_ = (const __nv_bfloat16*)(smem_dyn + s * STAGE_BYTES);
        const __nv_bfloat16* Bs_ = (const __nv_bfloat16*)(smem_dyn + s * STAGE_BYTES + TILE_BYTES);

        #pragma unroll
        for (int ks = 0; ks < 2; ++ks) {
            const int kb = ks * 16;
            uint32_t a[2][4];
            #pragma unroll
            for (int im = 0; im < 2; ++im) {
                int r0 = wm * 32 + im * 16 + g;
                int c0 = kb + 2 * tig;
                a[im][0] = *(const uint32_t*)(As_ + r0 * ROWH + c0);
                a[im][1] = *(const uint32_t*)(As_ + (r0 + 8) * ROWH + c0);
                a[im][2] = *(const uint32_t*)(As_ + r0 * ROWH + c0 + 8);
                a[im][3] = *(const uint32_t*)(As_ + (r0 + 8) * ROWH + c0 + 8);
            }
            #pragma unroll
            for (int in = 0; in < 8; ++in) {
                int n = wn * 64 + in * 8 + g;
                uint32_t b[2];
                b[0] = *(const uint32_t*)(Bs_ + n * ROWH + kb + 2 * tig);
                b[1] = *(const uint32_t*)(Bs_ + n * ROWH + kb + 2 * tig + 8);
                #pragma unroll
                for (int im = 0; im < 2; ++im)
                    mma16816(acc[im][in], a[im], b);
            }
        }
    }

    // write C tile
    #pragma unroll
    for (int im = 0; im < 2; ++im) {
        #pragma unroll
        for (int in = 0; in < 8; ++in) {
            int row = bm0 + wm * 32 + im * 16 + g;
            int col = n0 + wn * 64 + in * 8 + 2 * tig;
            float2 v0 = make_float2(acc[im][in][0], acc[im][in][1]);
            float2 v1 = make_float2(acc[im][in][2], acc[im][in][3]);
            *(float2*)(g_C + (size_t)row * NV + col) = v0;
            *(float2*)(g_C + (size_t)(row + 8) * NV + col) = v1;
        }
    }
}

// ---------------- fused epilogue ----------------
__device__ __forceinline__ float sigmoidf_(float v) { return 1.0f / (1.0f + expf(-v)); }

__global__ __launch_bounds__(256)
void srul_epilogue_kernel(const float* __restrict__ c_prev,
                          const float* __restrict__ bi,
                          const float* __restrict__ bf,
                          const float* __restrict__ bo,
                          const float* __restrict__ bxs,
                          const float* __restrict__ bxg,
                          const float* __restrict__ bhg,
                          float* __restrict__ out)
{
    int idx = blockIdx.x * blockDim.x + threadIdx.x;
    int v = idx * 4;
    if (v >= BATCH * HID) return;
    int b = v >> 10;
    int j = v & 1023;

    const float* row = g_C + (size_t)b * NV;
    float4 ri = *(const float4*)(row + j);
    float4 rf = *(const float4*)(row + 1024 + j);
    float4 ro = *(const float4*)(row + 2048 + j);
    float4 rc = *(const float4*)(row + 3072 + j);
    float4 rs = *(const float4*)(row + 4096 + j);
    float4 vbi  = *(const float4*)(bi + j);
    float4 vbf  = *(const float4*)(bf + j);
    float4 vbo  = *(const float4*)(bo + j);
    float4 vbxs = *(const float4*)(bxs + j);
    float4 vbxg = *(const float4*)(bxg + j);
    float4 vbhg = *(const float4*)(bhg + j);
    float4 vcp  = *(const float4*)(c_prev + (size_t)b * 1024 + j);

    float4 outh, outc;
    const float* pri = &ri.x; const float* prf = &rf.x; const float* pro = &ro.x;
    const float* prc = &rc.x; const float* prs = &rs.x;
    const float* pbi = &vbi.x; const float* pbf = &vbf.x; const float* pbo = &vbo.x;
    const float* pbxs = &vbxs.x; const float* pbxg = &vbxg.x; const float* pbhg = &vbhg.x;
    const float* pcp = &vcp.x;
    float* ph = &outh.x; float* pc = &outc.x;

    #pragma unroll
    for (int t = 0; t < 4; ++t) {
        float ig = sigmoidf_(pri[t] + pbi[t]);
        float fg = sigmoidf_(prf[t] + pbf[t]);
        float og = sigmoidf_(pro[t] + pbo[t]);
        float s  = prs[t] + pbxs[t];
        float cand = prc[t] + pbxg[t] + pbhg[t];
        float gg = tanhf(s * cand);
        float c  = fg * pcp[t] + ig * gg;
        ph[t] = og * tanhf(c);
        pc[t] = c;
    }

    *(float4*)(out + (size_t)b * 1024 + j) = outh;
    *(float4*)(out + (size_t)BATCH * HID + (size_t)b * 1024 + j) = outc;
}

// ---------------- launch ----------------
extern "C" void kernel_launch(void* const* d_in, const int* in_sizes, int n_in,
                              void* d_out, int out_size)
{
    const float* x      = (const float*)d_in[0];
    const float* h_prev = (const float*)d_in[1];
    const float* c_prev = (const float*)d_in[2];
    const float* Wi     = (const float*)d_in[3];
    const float* bi     = (const float*)d_in[4];
    const float* Wf     = (const float*)d_in[5];
    const float* bf     = (const float*)d_in[6];
    const float* Wo     = (const float*)d_in[7];
    const float* bo     = (const float*)d_in[8];
    const float* Wxs    = (const float*)d_in[9];
    const float* bxs    = (const float*)d_in[10];
    const float* Wxg    = (const float*)d_in[11];
    const float* bxg    = (const float*)d_in[12];
    const float* Whg    = (const float*)d_in[13];
    const float* bhg    = (const float*)d_in[14];
    float* out = (float*)d_out;

    cudaFuncSetAttribute(gemm_kernel, cudaFuncAttributeMaxDynamicSharedMemorySize, SMEM_DYN);

    convA_kernel<<<(BATCH * 2048) / 256, 256>>>(x, h_prev);
    convB_kernel<<<(NV * 2048) / 256, 256>>>(Wi, Wf, Wo, Wxs, Wxg, Whg);

    dim3 grid(BATCH / BM, NV / BN);   // 32 x 40
    gemm_kernel<<<grid, 256, SMEM_DYN>>>();

    int total_vec = (BATCH * HID) / 4;
    srul_epilogue_kernel<<<(total_vec + 255) / 256, 256>>>(c_prev, bi, bf, bo, bxs, bxg, bhg, out);
}